// round 14
// baseline (speedup 1.0000x reference)
#include <cuda_runtime.h>
#include <cuda_bf16.h>

#define N_NODES 6144
#define NFEAT   512
#define NHID    256
#define NHEADS  4
#define DHEAD   64
#define NEMBED  128
#define LRELU_ALPHA 0.2f
#define MAXDEG  256
#define KCAT    1536           // 3 * NFEAT (split-bf16 concat, k1)
#define KCAT4   768            // 3 * NHID  (split-bf16 concat, k4)

typedef unsigned int u32;

// Scratch (device globals; no runtime allocation allowed)
__device__ float g_whcat[N_NODES * NHID];
__device__ float g_s[NHEADS * N_NODES];
__device__ float g_t[NHEADS * N_NODES];
__device__ __nv_bfloat16 g_abf[N_NODES * KCAT];   // [x_hi | x_hi | x_lo]
__device__ __nv_bfloat16 g_bbf[NHID * KCAT];      // [w_hi | w_lo | w_hi]
__device__ __nv_bfloat16 g_h4a[N_NODES * KCAT4];  // [h_hi | h_hi | h_lo]
__device__ __nv_bfloat16 g_b4[NEMBED * KCAT4];    // [w_hi | w_lo | w_hi]
__device__ int g_nbr[N_NODES * MAXDEG];           // compacted neighbor lists
__device__ int g_deg[N_NODES];

// ---------------------------------------------------------------------------
__device__ __forceinline__ void hmma16816(
    float& c0, float& c1, float& c2, float& c3,
    u32 a0, u32 a1, u32 a2, u32 a3, u32 b0, u32 b1)
{
    asm volatile(
        "mma.sync.aligned.m16n8k16.row.col.f32.bf16.bf16.f32 "
        "{%0,%1,%2,%3}, {%4,%5,%6,%7}, {%8,%9}, {%0,%1,%2,%3};\n"
        : "+f"(c0), "+f"(c1), "+f"(c2), "+f"(c3)
        : "r"(a0), "r"(a1), "r"(a2), "r"(a3), "r"(b0), "r"(b1));
}
__device__ __forceinline__ void ldsm4(u32& r0, u32& r1, u32& r2, u32& r3, u32 addr)
{
    asm volatile("ldmatrix.sync.aligned.m8n8.x4.shared.b16 {%0,%1,%2,%3}, [%4];"
                 : "=r"(r0), "=r"(r1), "=r"(r2), "=r"(r3) : "r"(addr));
}
__device__ __forceinline__ void cp16(u32 saddr, const void* gptr)
{
    asm volatile("cp.async.cg.shared.global [%0], [%1], 16;" :: "r"(saddr), "l"(gptr));
}
#define CP_COMMIT() asm volatile("cp.async.commit_group;" ::: "memory")
#define CP_WAIT0()  asm volatile("cp.async.wait_group 0;" ::: "memory")
#define CP_WAIT1()  asm volatile("cp.async.wait_group 1;" ::: "memory")

__device__ __forceinline__ u32 smem_u32(const void* p)
{
    u32 a;
    asm("{ .reg .u64 t; cvta.to.shared.u64 t, %1; cvt.u32.u64 %0, t; }"
        : "=r"(a) : "l"(p));
    return a;
}

// ---------------------------------------------------------------------------
// P: all three split-bf16 preps fused into one launch, sectioned by blockIdx.
// ---------------------------------------------------------------------------
#define PB_A 3072
#define PB_B 512
#define PB_L 128

__global__ __launch_bounds__(256) void p_prep(
    const float* __restrict__ x, const float* __restrict__ W,
    const float* __restrict__ lin_w,
    __nv_bfloat16* __restrict__ abf, __nv_bfloat16* __restrict__ bbf,
    __nv_bfloat16* __restrict__ b4)
{
    const int b   = blockIdx.x;
    const int tid = threadIdx.x;

    if (b < PB_A) {
        int idx = b * 256 + tid;
        int m = idx >> 7;
        int kq = (idx & 127) << 2;
        float4 v = *(const float4*)(x + (size_t)m * NFEAT + kq);
        float vv[4] = {v.x, v.y, v.z, v.w};
        __nv_bfloat16 hi[4], lo[4];
#pragma unroll
        for (int i = 0; i < 4; i++) {
            hi[i] = __float2bfloat16(vv[i]);
            lo[i] = __float2bfloat16(vv[i] - __bfloat162float(hi[i]));
        }
        __nv_bfloat16* base = abf + (size_t)m * KCAT + kq;
        *(uint2*)(base)        = *(uint2*)hi;
        *(uint2*)(base + 512)  = *(uint2*)hi;
        *(uint2*)(base + 1024) = *(uint2*)lo;
    } else if (b < PB_A + PB_B) {
        int idx = (b - PB_A) * 256 + tid;
        int n = idx >> 9;
        int k = idx & 511;
        int h = n >> 6, d = n & 63;
        float v = W[((size_t)h * NFEAT + k) * DHEAD + d];
        __nv_bfloat16 hi = __float2bfloat16(v);
        __nv_bfloat16 lo = __float2bfloat16(v - __bfloat162float(hi));
        __nv_bfloat16* base = bbf + (size_t)n * KCAT + k;
        base[0]    = hi;
        base[512]  = lo;
        base[1024] = hi;
    } else {
        int idx = (b - PB_A - PB_B) * 256 + tid;
        int n = idx >> 8;
        int k = idx & 255;
        float v = lin_w[(size_t)n * NHID + k];
        __nv_bfloat16 hi = __float2bfloat16(v);
        __nv_bfloat16 lo = __float2bfloat16(v - __bfloat162float(hi));
        __nv_bfloat16* base = b4 + (size_t)n * KCAT4 + k;
        base[0]   = hi;
        base[256] = lo;
        base[512] = hi;
    }
}

// ---------------------------------------------------------------------------
// K1F: FUSED kernel, BK=64 (24 k-iters, half the barriers, double cp MLP),
//      2-stage ring, 36KB smem (~6 CTAs/SM).
//   blocks [0, 384):      HMMA GEMM whcat = A' @ B'^T (BM=64, BN=64)
//   blocks [384, 6528):   adjacency scan -> g_nbr/g_deg
// ---------------------------------------------------------------------------
#define BK1     64
#define SSTR1   36             // u32 words per smem row (32 data + 4 pad)
#define K1_NIT  (KCAT / BK1)   // 24
#define NB_GEMM 384

__global__ __launch_bounds__(128) void k1_fused(
    const __nv_bfloat16* __restrict__ abf, const __nv_bfloat16* __restrict__ bbf,
    float* __restrict__ C,
    const int* __restrict__ adj, int* __restrict__ nbr, int* __restrict__ deg)
{
    __shared__ u32 As[2][64][SSTR1];
    __shared__ u32 Bs[2][64][SSTR1];

    const int bid = blockIdx.x;
    const int tid = threadIdx.x;

    if (bid >= NB_GEMM) {
        // ---------------- scan branch ----------------
        __shared__ int scount;
        const int i    = bid - NB_GEMM;
        const int lane = tid & 31;
        if (tid == 0) scount = 0;
        __syncthreads();

        const int4* arow = (const int4*)(adj + (size_t)i * N_NODES);
        int4 v[12];
#pragma unroll
        for (int q = 0; q < 12; q++) v[q] = arow[tid + q * 128];

        int cnt = 0;
#pragma unroll
        for (int q = 0; q < 12; q++)
            cnt += (v[q].x != 0) + (v[q].y != 0) + (v[q].z != 0) + (v[q].w != 0);

        int inc = cnt;
#pragma unroll
        for (int o = 1; o < 32; o <<= 1) {
            int nb = __shfl_up_sync(0xffffffffu, inc, o);
            if (lane >= o) inc += nb;
        }
        int excl = inc - cnt;
        int wtot = __shfl_sync(0xffffffffu, inc, 31);

        int wbase = 0;
        if (lane == 31 && wtot > 0) wbase = atomicAdd(&scount, wtot);
        wbase = __shfl_sync(0xffffffffu, wbase, 31);

        int* row = nbr + (size_t)i * MAXDEG;
        int p = wbase + excl;
#pragma unroll
        for (int q = 0; q < 12; q++) {
            int c = (tid + q * 128) * 4;
            if (v[q].x) { if (p < MAXDEG) row[p] = c + 0; p++; }
            if (v[q].y) { if (p < MAXDEG) row[p] = c + 1; p++; }
            if (v[q].z) { if (p < MAXDEG) row[p] = c + 2; p++; }
            if (v[q].w) { if (p < MAXDEG) row[p] = c + 3; p++; }
        }
        __syncthreads();
        if (tid == 0) deg[i] = min(scount, MAXDEG);
        return;
    }

    // ---------------- GEMM branch (BK=64, 2-stage) ----------------
    const int wid  = tid >> 5;
    const int lane = tid & 31;
    const int g    = lane >> 2;
    const int tig  = lane & 3;
    const int m0   = (bid >> 2) * 64;
    const int n0   = (bid & 3) * 64;
    const int wm   = (wid & 1) * 32;
    const int wn   = (wid >> 1) * 32;

    const u32 sA = smem_u32(As);
    const u32 sB = smem_u32(Bs);

    float acc[2][4][4];
#pragma unroll
    for (int mi = 0; mi < 2; mi++)
#pragma unroll
        for (int ni = 0; ni < 4; ni++)
#pragma unroll
            for (int q = 0; q < 4; q++) acc[mi][ni][q] = 0.f;

    const u32 a_frag_off = ((u32)(wm + (lane & 15)) * SSTR1 + ((lane >> 4) << 2)) << 2;
    const u32 b_frag_off = ((u32)(wn + (lane & 7) + ((lane >> 4) << 3)) * SSTR1
                            + (((lane >> 3) & 1) << 2)) << 2;

    // tile load: 64 rows x 64 bf16 = 512 16B-chunks per matrix; 4 per thread
#define K1_LOAD(stg, kk)                                                        \
    do {                                                                        \
        _Pragma("unroll")                                                       \
        for (int ps = 0; ps < 4; ps++) {                                        \
            int chunk = tid + ps * 128;                                         \
            int row = chunk >> 3;                                               \
            int wq  = (chunk & 7) << 2;                                         \
            cp16(sA + (((stg) * 64 + row) * SSTR1 + wq) * 4,                    \
                 abf + (size_t)(m0 + row) * KCAT + (kk) + wq * 2);              \
            cp16(sB + (((stg) * 64 + row) * SSTR1 + wq) * 4,                    \
                 bbf + (size_t)(n0 + row) * KCAT + (kk) + wq * 2);              \
        }                                                                       \
        CP_COMMIT();                                                            \
    } while (0)

    K1_LOAD(0, 0);

    for (int it = 0; it < K1_NIT; it++) {
        const int buf = it & 1;
        if (it + 1 < K1_NIT) {
            K1_LOAD(buf ^ 1, (it + 1) * BK1);
            CP_WAIT1();
        } else {
            CP_WAIT0();
        }
        __syncthreads();

        const u32 aB = sA + (u32)(buf * 64 * SSTR1 * 4) + a_frag_off;
        const u32 bB = sB + (u32)(buf * 64 * SSTR1 * 4) + b_frag_off;
#pragma unroll
        for (int ks = 0; ks < 4; ks++) {
            const u32 kOff = (u32)(ks * 8 * 4);
            u32 a[2][4];
#pragma unroll
            for (int mi = 0; mi < 2; mi++)
                ldsm4(a[mi][0], a[mi][1], a[mi][2], a[mi][3],
                      aB + (u32)(mi * 16 * SSTR1 * 4) + kOff);
            u32 b[2][4];
#pragma unroll
            for (int nj = 0; nj < 2; nj++)
                ldsm4(b[nj][0], b[nj][1], b[nj][2], b[nj][3],
                      bB + (u32)(nj * 16 * SSTR1 * 4) + kOff);
#pragma unroll
            for (int mi = 0; mi < 2; mi++)
#pragma unroll
                for (int nj = 0; nj < 2; nj++) {
                    hmma16816(acc[mi][nj*2+0][0], acc[mi][nj*2+0][1],
                              acc[mi][nj*2+0][2], acc[mi][nj*2+0][3],
                              a[mi][0], a[mi][1], a[mi][2], a[mi][3],
                              b[nj][0], b[nj][1]);
                    hmma16816(acc[mi][nj*2+1][0], acc[mi][nj*2+1][1],
                              acc[mi][nj*2+1][2], acc[mi][nj*2+1][3],
                              a[mi][0], a[mi][1], a[mi][2], a[mi][3],
                              b[nj][2], b[nj][3]);
                }
        }
        __syncthreads();
    }

#pragma unroll
    for (int mi = 0; mi < 2; mi++) {
        const int r0 = m0 + wm + mi * 16 + g;
#pragma unroll
        for (int ni = 0; ni < 4; ni++) {
            const int c0 = n0 + wn + ni * 8 + tig * 2;
            *(float2*)(C + (size_t)r0 * NHID + c0) =
                make_float2(acc[mi][ni][0], acc[mi][ni][1]);
            *(float2*)(C + (size_t)(r0 + 8) * NHID + c0) =
                make_float2(acc[mi][ni][2], acc[mi][ni][3]);
        }
    }
#undef K1_LOAD
}

// ---------------------------------------------------------------------------
// K2: coalesced s/t — one warp per node.
// ---------------------------------------------------------------------------
__global__ __launch_bounds__(256) void k2_st(
    const float* __restrict__ wh, const float* __restrict__ a_src,
    const float* __restrict__ a_dst,
    float* __restrict__ s, float* __restrict__ t)
{
    __shared__ float asf[NHID], adf[NHID];
    const int tid = threadIdx.x;
    if (tid < NHID) {
        asf[tid] = a_src[tid];
        adf[tid] = a_dst[tid];
    }
    __syncthreads();

    const int wid  = tid >> 5;
    const int lane = tid & 31;
    const int node = blockIdx.x * 8 + wid;
    if (node >= N_NODES) return;

    const float* row = wh + (size_t)node * NHID + lane * 8;
    float4 v0 = *(const float4*)(row + 0);
    float4 v1 = *(const float4*)(row + 4);
    const float* as = asf + lane * 8;
    const float* ad = adf + lane * 8;
    float ss = v0.x * as[0] + v0.y * as[1] + v0.z * as[2] + v0.w * as[3]
             + v1.x * as[4] + v1.y * as[5] + v1.z * as[6] + v1.w * as[7];
    float tt = v0.x * ad[0] + v0.y * ad[1] + v0.z * ad[2] + v0.w * ad[3]
             + v1.x * ad[4] + v1.y * ad[5] + v1.z * ad[6] + v1.w * ad[7];
#pragma unroll
    for (int o = 4; o; o >>= 1) {
        ss += __shfl_xor_sync(0xffffffffu, ss, o);
        tt += __shfl_xor_sync(0xffffffffu, tt, o);
    }
    if ((lane & 7) == 0) {
        int h = lane >> 3;
        s[h * N_NODES + node] = ss;
        t[h * N_NODES + node] = tt;
    }
}

// ---------------------------------------------------------------------------
// K3: attention from precompacted lists. sidx holds PREMULTIPLIED offsets
//     (col << 8 = col*NHID) to drop the shift from the gather loop body.
// ---------------------------------------------------------------------------
__global__ __launch_bounds__(256) void k3_attn(
    const int* __restrict__ nbr, const int* __restrict__ degv,
    const float* __restrict__ wh,
    const float* __restrict__ s, const float* __restrict__ t,
    __nv_bfloat16* __restrict__ h4a)
{
    __shared__ int   sidx[MAXDEG];     // col * NHID
    __shared__ float sw[NHEADS * MAXDEG];
    __shared__ float srs[NHEADS];

    const int i   = blockIdx.x;
    const int tid = threadIdx.x;
    const int deg = degv[i];

    for (int j = tid; j < deg; j += 256) sidx[j] = nbr[(size_t)i * MAXDEG + j] << 8;
    __syncthreads();

    for (int m = tid; m < deg * NHEADS; m += 256) {
        int j = m >> 2;
        int h = m & 3;
        int jj = sidx[j] >> 8;
        float e = s[h * N_NODES + i] + t[h * N_NODES + jj];
        e = e > 0.f ? e : LRELU_ALPHA * e;
        sw[h * MAXDEG + j] = e;
    }
    __syncthreads();

    const int warp = tid >> 5;
    const int lane = tid & 31;
    if (warp < NHEADS) {
        const int h = warp;
        float mx = -3.4e38f;
        for (int j = lane; j < deg; j += 32) mx = fmaxf(mx, sw[h * MAXDEG + j]);
#pragma unroll
        for (int o = 16; o; o >>= 1) mx = fmaxf(mx, __shfl_xor_sync(0xffffffffu, mx, o));
        float sum = 0.f;
        for (int j = lane; j < deg; j += 32) {
            float w = __expf(sw[h * MAXDEG + j] - mx);
            sw[h * MAXDEG + j] = w;
            sum += w;
        }
#pragma unroll
        for (int o = 16; o; o >>= 1) sum += __shfl_xor_sync(0xffffffffu, sum, o);
        if (lane == 0) srs[h] = (sum > 0.f) ? 1.f / sum : 0.f;
    }
    __syncthreads();

    const int h = tid >> 6;
    float acc = 0.f;
    const float* whb = wh + tid;
    const float* swh = sw + h * MAXDEG;
#pragma unroll 4
    for (int j = 0; j < deg; j++) {
        int off = sidx[j];                       // already col*NHID
        acc += swh[j] * whb[(size_t)off];
    }
    acc *= srs[h];
    acc = acc > 0.f ? acc : (__expf(acc) - 1.f);

    __nv_bfloat16 hi = __float2bfloat16(acc);
    __nv_bfloat16 lo = __float2bfloat16(acc - __bfloat162float(hi));
    __nv_bfloat16* base = h4a + (size_t)i * KCAT4 + tid;
    base[0]   = hi;
    base[256] = hi;
    base[512] = lo;
}

// ---------------------------------------------------------------------------
// K4: HMMA GEMM  out = elu(h' @ lin_w'^T + b)   (unchanged, BK=32/stride 20)
// ---------------------------------------------------------------------------
#define BK4   32
#define SSTR4 20

__global__ __launch_bounds__(256) void k4_mma(
    const __nv_bfloat16* __restrict__ h4a, const __nv_bfloat16* __restrict__ b4,
    const float* __restrict__ lin_b, float* __restrict__ out)
{
    __shared__ u32 As[32][SSTR4];
    __shared__ u32 Bs[128][SSTR4];

    const int tid  = threadIdx.x;
    const int wid  = tid >> 5;
    const int lane = tid & 31;
    const int g    = lane >> 2;
    const int tig  = lane & 3;
    const int m0   = blockIdx.x * 32;
    const int wn   = wid * 16;

    float acc[2][2][4];
#pragma unroll
    for (int mi = 0; mi < 2; mi++)
#pragma unroll
        for (int ni = 0; ni < 2; ni++)
#pragma unroll
            for (int q = 0; q < 4; q++) acc[mi][ni][q] = 0.f;

    const int l_row = tid >> 2;
    const int l_wq  = (tid & 3) << 2;

    for (int kk = 0; kk < KCAT4; kk += BK4) {
        if (tid < 128) {
            uint4 va = *(const uint4*)(h4a + (size_t)(m0 + l_row) * KCAT4 + kk + l_wq * 2);
            *(uint4*)&As[l_row][l_wq] = va;
        }
#pragma unroll
        for (int it = 0; it < 2; it++) {
            int row = l_row + it * 64;
            uint4 vb = *(const uint4*)(b4 + (size_t)row * KCAT4 + kk + l_wq * 2);
            *(uint4*)&Bs[row][l_wq] = vb;
        }
        __syncthreads();

#pragma unroll
        for (int ks = 0; ks < 2; ks++) {
            const int kw = ks * 8;
            u32 a[2][4];
#pragma unroll
            for (int mi = 0; mi < 2; mi++) {
                const int r = mi * 16;
                a[mi][0] = As[r + g    ][kw + tig];
                a[mi][1] = As[r + g + 8][kw + tig];
                a[mi][2] = As[r + g    ][kw + tig + 4];
                a[mi][3] = As[r + g + 8][kw + tig + 4];
            }
            u32 b[2][2];
#pragma unroll
            for (int ni = 0; ni < 2; ni++) {
                const int n = wn + ni * 8 + g;
                b[ni][0] = Bs[n][kw + tig];
                b[ni][1] = Bs[n][kw + tig + 4];
            }
#pragma unroll
            for (int mi = 0; mi < 2; mi++)
#pragma unroll
                for (int ni = 0; ni < 2; ni++)
                    hmma16816(acc[mi][ni][0], acc[mi][ni][1],
                              acc[mi][ni][2], acc[mi][ni][3],
                              a[mi][0], a[mi][1], a[mi][2], a[mi][3],
                              b[ni][0], b[ni][1]);
        }
        __syncthreads();
    }

#pragma unroll
    for (int mi = 0; mi < 2; mi++) {
        const int r0 = m0 + mi * 16 + g;
#pragma unroll
        for (int ni = 0; ni < 2; ni++) {
            const int c0 = wn + ni * 8 + tig * 2;
            float b0 = lin_b[c0], b1 = lin_b[c0 + 1];
            float v0 = acc[mi][ni][0] + b0;
            float v1 = acc[mi][ni][1] + b1;
            float v2 = acc[mi][ni][2] + b0;
            float v3 = acc[mi][ni][3] + b1;
            v0 = v0 > 0.f ? v0 : (__expf(v0) - 1.f);
            v1 = v1 > 0.f ? v1 : (__expf(v1) - 1.f);
            v2 = v2 > 0.f ? v2 : (__expf(v2) - 1.f);
            v3 = v3 > 0.f ? v3 : (__expf(v3) - 1.f);
            *(float2*)(out + (size_t)r0 * NEMBED + c0) = make_float2(v0, v1);
            *(float2*)(out + (size_t)(r0 + 8) * NEMBED + c0) = make_float2(v2, v3);
        }
    }
}

// ---------------------------------------------------------------------------
extern "C" void kernel_launch(void* const* d_in, const int* in_sizes, int n_in,
                              void* d_out, int out_size)
{
    const float* x     = (const float*)d_in[0];
    const int*   adj   = (const int*)  d_in[1];
    const float* W     = (const float*)d_in[2];
    const float* a_src = (const float*)d_in[3];
    const float* a_dst = (const float*)d_in[4];
    const float* lin_w = (const float*)d_in[5];
    const float* lin_b = (const float*)d_in[6];
    float* out = (float*)d_out;

    float* whcat; cudaGetSymbolAddress((void**)&whcat, g_whcat);
    float* s;     cudaGetSymbolAddress((void**)&s, g_s);
    float* t;     cudaGetSymbolAddress((void**)&t, g_t);
    __nv_bfloat16* abf; cudaGetSymbolAddress((void**)&abf, g_abf);
    __nv_bfloat16* bbf; cudaGetSymbolAddress((void**)&bbf, g_bbf);
    __nv_bfloat16* h4a; cudaGetSymbolAddress((void**)&h4a, g_h4a);
    __nv_bfloat16* b4;  cudaGetSymbolAddress((void**)&b4, g_b4);
    int* nbr; cudaGetSymbolAddress((void**)&nbr, g_nbr);
    int* deg; cudaGetSymbolAddress((void**)&deg, g_deg);

    p_prep<<<PB_A + PB_B + PB_L, 256>>>(x, W, lin_w, abf, bbf, b4);

    k1_fused<<<NB_GEMM + N_NODES, 128>>>(abf, bbf, whcat, adj, nbr, deg);

    k2_st<<<N_NODES / 8, 256>>>(whcat, a_src, a_dst, s, t);

    k3_attn<<<N_NODES, 256>>>(nbr, deg, whcat, s, t, h4a);

    k4_mma<<<N_NODES / 32, 256>>>(h4a, b4, lin_b, out);
}

// round 15
// speedup vs baseline: 1.1324x; 1.1324x over previous
#include <cuda_runtime.h>
#include <cuda_bf16.h>

#define N_NODES 6144
#define NFEAT   512
#define NHID    256
#define NHEADS  4
#define DHEAD   64
#define NEMBED  128
#define LRELU_ALPHA 0.2f
#define MAXDEG  256
#define KCAT    1536           // logical K (3 * NFEAT) for the split-bf16 GEMM
#define KCATA   1024           // A' physical row: [x_hi | x_lo]
#define KCAT4   768            // 3 * NHID  (split-bf16 concat, k4)

typedef unsigned int u32;

// Scratch (device globals; no runtime allocation allowed)
__device__ float g_whcat[N_NODES * NHID];
__device__ float g_s[NHEADS * N_NODES];
__device__ float g_t[NHEADS * N_NODES];
__device__ __nv_bfloat16 g_abf[N_NODES * KCATA];  // [x_hi | x_lo]
__device__ __nv_bfloat16 g_bbf[NHID * KCAT];      // [w_hi | w_lo | w_hi]
__device__ __nv_bfloat16 g_h4a[N_NODES * KCAT4];  // [h_hi | h_hi | h_lo]
__device__ __nv_bfloat16 g_b4[NEMBED * KCAT4];    // [w_hi | w_lo | w_hi]
__device__ int g_nbr[N_NODES * MAXDEG];           // compacted neighbor lists
__device__ int g_deg[N_NODES];

// ---------------------------------------------------------------------------
__device__ __forceinline__ void hmma16816(
    float& c0, float& c1, float& c2, float& c3,
    u32 a0, u32 a1, u32 a2, u32 a3, u32 b0, u32 b1)
{
    asm volatile(
        "mma.sync.aligned.m16n8k16.row.col.f32.bf16.bf16.f32 "
        "{%0,%1,%2,%3}, {%4,%5,%6,%7}, {%8,%9}, {%0,%1,%2,%3};\n"
        : "+f"(c0), "+f"(c1), "+f"(c2), "+f"(c3)
        : "r"(a0), "r"(a1), "r"(a2), "r"(a3), "r"(b0), "r"(b1));
}
__device__ __forceinline__ void ldsm4(u32& r0, u32& r1, u32& r2, u32& r3, u32 addr)
{
    asm volatile("ldmatrix.sync.aligned.m8n8.x4.shared.b16 {%0,%1,%2,%3}, [%4];"
                 : "=r"(r0), "=r"(r1), "=r"(r2), "=r"(r3) : "r"(addr));
}
__device__ __forceinline__ void cp16(u32 saddr, const void* gptr)
{
    asm volatile("cp.async.cg.shared.global [%0], [%1], 16;" :: "r"(saddr), "l"(gptr));
}
#define CP_COMMIT() asm volatile("cp.async.commit_group;" ::: "memory")
#define CP_WAIT0()  asm volatile("cp.async.wait_group 0;" ::: "memory")
#define CP_WAIT1()  asm volatile("cp.async.wait_group 1;" ::: "memory")

__device__ __forceinline__ u32 smem_u32(const void* p)
{
    u32 a;
    asm("{ .reg .u64 t; cvta.to.shared.u64 t, %1; cvt.u32.u64 %0, t; }"
        : "=r"(a) : "l"(p));
    return a;
}

// ---------------------------------------------------------------------------
// P: split-bf16 preps + s/t zeroing fused in one launch, sectioned by blockIdx.
// ---------------------------------------------------------------------------
#define PB_A 3072
#define PB_B 512
#define PB_L 128
#define PB_Z 48

__global__ __launch_bounds__(256) void p_prep(
    const float* __restrict__ x, const float* __restrict__ W,
    const float* __restrict__ lin_w,
    __nv_bfloat16* __restrict__ abf, __nv_bfloat16* __restrict__ bbf,
    __nv_bfloat16* __restrict__ b4,
    float* __restrict__ s, float* __restrict__ t)
{
    const int b   = blockIdx.x;
    const int tid = threadIdx.x;

    if (b < PB_A) {
        int idx = b * 256 + tid;
        int m = idx >> 7;
        int kq = (idx & 127) << 2;
        float4 v = *(const float4*)(x + (size_t)m * NFEAT + kq);
        float vv[4] = {v.x, v.y, v.z, v.w};
        __nv_bfloat16 hi[4], lo[4];
#pragma unroll
        for (int i = 0; i < 4; i++) {
            hi[i] = __float2bfloat16(vv[i]);
            lo[i] = __float2bfloat16(vv[i] - __bfloat162float(hi[i]));
        }
        __nv_bfloat16* base = abf + (size_t)m * KCATA + kq;
        *(uint2*)(base)       = *(uint2*)hi;
        *(uint2*)(base + 512) = *(uint2*)lo;
    } else if (b < PB_A + PB_B) {
        int idx = (b - PB_A) * 256 + tid;
        int n = idx >> 9;
        int k = idx & 511;
        int h = n >> 6, d = n & 63;
        float v = W[((size_t)h * NFEAT + k) * DHEAD + d];
        __nv_bfloat16 hi = __float2bfloat16(v);
        __nv_bfloat16 lo = __float2bfloat16(v - __bfloat162float(hi));
        __nv_bfloat16* base = bbf + (size_t)n * KCAT + k;
        base[0]    = hi;
        base[512]  = lo;
        base[1024] = hi;
    } else if (b < PB_A + PB_B + PB_L) {
        int idx = (b - PB_A - PB_B) * 256 + tid;
        int n = idx >> 8;
        int k = idx & 255;
        float v = lin_w[(size_t)n * NHID + k];
        __nv_bfloat16 hi = __float2bfloat16(v);
        __nv_bfloat16 lo = __float2bfloat16(v - __bfloat162float(hi));
        __nv_bfloat16* base = b4 + (size_t)n * KCAT4 + k;
        base[0]   = hi;
        base[256] = lo;
        base[512] = hi;
    } else {
        // zero g_s / g_t (6144*4 floats each = 6144 float4 each)
        int idx = (b - PB_A - PB_B - PB_L) * 256 + tid;
        float4 z = make_float4(0.f, 0.f, 0.f, 0.f);
        if (idx < 6144) ((float4*)s)[idx] = z;
        else            ((float4*)t)[idx - 6144] = z;
    }
}

// ---------------------------------------------------------------------------
// K1F: FUSED kernel (R13 BK=32/SSTR=20 schedule) + s/t epilogue (k2 folded).
//   blocks [0, 384):      HMMA GEMM whcat = A' @ B'^T, one head per block
//   blocks [384, 6528):   adjacency scan -> g_nbr/g_deg
// ---------------------------------------------------------------------------
#define BK      32
#define SSTR    20
#define K1_NIT  (KCAT / BK)
#define NB_GEMM 384

__global__ __launch_bounds__(128) void k1_fused(
    const __nv_bfloat16* __restrict__ abf, const __nv_bfloat16* __restrict__ bbf,
    float* __restrict__ C,
    const int* __restrict__ adj, int* __restrict__ nbr, int* __restrict__ deg,
    const float* __restrict__ a_src, const float* __restrict__ a_dst,
    float* __restrict__ s, float* __restrict__ t)
{
    __shared__ u32 As[2][64][SSTR];
    __shared__ u32 Bs[2][64][SSTR];

    const int bid = blockIdx.x;
    const int tid = threadIdx.x;

    if (bid >= NB_GEMM) {
        // ---------------- scan branch ----------------
        __shared__ int scount;
        const int i    = bid - NB_GEMM;
        const int lane = tid & 31;
        if (tid == 0) scount = 0;
        __syncthreads();

        const int4* arow = (const int4*)(adj + (size_t)i * N_NODES);
        int4 v[12];
#pragma unroll
        for (int q = 0; q < 12; q++) v[q] = arow[tid + q * 128];

        int cnt = 0;
#pragma unroll
        for (int q = 0; q < 12; q++)
            cnt += (v[q].x != 0) + (v[q].y != 0) + (v[q].z != 0) + (v[q].w != 0);

        int inc = cnt;
#pragma unroll
        for (int o = 1; o < 32; o <<= 1) {
            int nb = __shfl_up_sync(0xffffffffu, inc, o);
            if (lane >= o) inc += nb;
        }
        int excl = inc - cnt;
        int wtot = __shfl_sync(0xffffffffu, inc, 31);

        int wbase = 0;
        if (lane == 31 && wtot > 0) wbase = atomicAdd(&scount, wtot);
        wbase = __shfl_sync(0xffffffffu, wbase, 31);

        int* row = nbr + (size_t)i * MAXDEG;
        int p = wbase + excl;
#pragma unroll
        for (int q = 0; q < 12; q++) {
            int c = (tid + q * 128) * 4;
            if (v[q].x) { if (p < MAXDEG) row[p] = c + 0; p++; }
            if (v[q].y) { if (p < MAXDEG) row[p] = c + 1; p++; }
            if (v[q].z) { if (p < MAXDEG) row[p] = c + 2; p++; }
            if (v[q].w) { if (p < MAXDEG) row[p] = c + 3; p++; }
        }
        __syncthreads();
        if (tid == 0) deg[i] = min(scount, MAXDEG);
        return;
    }

    // ---------------- GEMM branch (R13-proven 2-stage) ----------------
    const int wid  = tid >> 5;
    const int lane = tid & 31;
    const int g    = lane >> 2;
    const int tig  = lane & 3;
    const int m0   = (bid >> 2) * 64;
    const int n0   = (bid & 3) * 64;       // == head * 64
    const int wm   = (wid & 1) * 32;
    const int wn   = (wid >> 1) * 32;

    const u32 sA = smem_u32(As);
    const u32 sB = smem_u32(Bs);

    float acc[2][4][4];
#pragma unroll
    for (int mi = 0; mi < 2; mi++)
#pragma unroll
        for (int ni = 0; ni < 4; ni++)
#pragma unroll
            for (int q = 0; q < 4; q++) acc[mi][ni][q] = 0.f;

    const int l_row = tid >> 2;
    const int l_wq  = (tid & 3) << 2;
    const int l_col = l_wq << 1;

    const u32 a_frag_off = ((u32)(wm + (lane & 15)) * SSTR + ((lane >> 4) << 2)) << 2;
    const u32 b_frag_off = ((u32)(wn + (lane & 7) + ((lane >> 4) << 3)) * SSTR
                            + (((lane >> 3) & 1) << 2)) << 2;

    // A' is stored dedup'd: [x_hi | x_lo] (1024/row). Logical K remap:
    //   kk in [0,512)     -> akk = kk        (x_hi, pairs w_hi)
    //   kk in [512,1024)  -> akk = kk - 512  (x_hi, pairs w_lo)
    //   kk in [1024,1536) -> akk = kk - 512  (x_lo, pairs w_hi)
#define K1_LOAD(stg, kk)                                                        \
    do {                                                                        \
        const int akk = (kk) < 512 ? (kk) : (kk) - 512;                         \
        _Pragma("unroll")                                                       \
        for (int ps = 0; ps < 2; ps++) {                                        \
            int row = l_row + ps * 32;                                          \
            cp16(sA + (((stg) * 64 + row) * SSTR + l_wq) * 4,                   \
                 abf + (size_t)(m0 + row) * KCATA + akk + l_col);               \
            cp16(sB + (((stg) * 64 + row) * SSTR + l_wq) * 4,                   \
                 bbf + (size_t)(n0 + row) * KCAT + (kk) + l_col);               \
        }                                                                       \
        CP_COMMIT();                                                            \
    } while (0)

    K1_LOAD(0, 0);

    for (int it = 0; it < K1_NIT; it++) {
        const int buf = it & 1;
        if (it + 1 < K1_NIT) {
            K1_LOAD(buf ^ 1, (it + 1) * BK);
            CP_WAIT1();
        } else {
            CP_WAIT0();
        }
        __syncthreads();

        const u32 aB = sA + (u32)(buf * 64 * SSTR * 4) + a_frag_off;
        const u32 bB = sB + (u32)(buf * 64 * SSTR * 4) + b_frag_off;
#pragma unroll
        for (int ks = 0; ks < 2; ks++) {
            const u32 kOff = (u32)(ks * 8 * 4);
            u32 a[2][4];
#pragma unroll
            for (int mi = 0; mi < 2; mi++)
                ldsm4(a[mi][0], a[mi][1], a[mi][2], a[mi][3],
                      aB + (u32)(mi * 16 * SSTR * 4) + kOff);
            u32 b[2][4];
#pragma unroll
            for (int nj = 0; nj < 2; nj++)
                ldsm4(b[nj][0], b[nj][1], b[nj][2], b[nj][3],
                      bB + (u32)(nj * 16 * SSTR * 4) + kOff);
#pragma unroll
            for (int mi = 0; mi < 2; mi++)
#pragma unroll
                for (int nj = 0; nj < 2; nj++) {
                    hmma16816(acc[mi][nj*2+0][0], acc[mi][nj*2+0][1],
                              acc[mi][nj*2+0][2], acc[mi][nj*2+0][3],
                              a[mi][0], a[mi][1], a[mi][2], a[mi][3],
                              b[nj][0], b[nj][1]);
                    hmma16816(acc[mi][nj*2+1][0], acc[mi][nj*2+1][1],
                              acc[mi][nj*2+1][2], acc[mi][nj*2+1][3],
                              a[mi][0], a[mi][1], a[mi][2], a[mi][3],
                              b[nj][2], b[nj][3]);
                }
        }
        __syncthreads();
    }

    // ---- epilogue 1: store whcat tile ----
#pragma unroll
    for (int mi = 0; mi < 2; mi++) {
        const int r0 = m0 + wm + mi * 16 + g;
#pragma unroll
        for (int ni = 0; ni < 4; ni++) {
            const int c0 = n0 + wn + ni * 8 + tig * 2;
            *(float2*)(C + (size_t)r0 * NHID + c0) =
                make_float2(acc[mi][ni][0], acc[mi][ni][1]);
            *(float2*)(C + (size_t)(r0 + 8) * NHID + c0) =
                make_float2(acc[mi][ni][2], acc[mi][ni][3]);
        }
    }

    // ---- epilogue 2 (k2 folded): partial s/t for this block's head ----
    {
        const int h = bid & 3;
        const float* asrc = a_src + h * DHEAD;
        const float* adst = a_dst + h * DHEAD;
#pragma unroll
        for (int mi = 0; mi < 2; mi++) {
            float sp0 = 0.f, sp1 = 0.f, tp0 = 0.f, tp1 = 0.f;
#pragma unroll
            for (int ni = 0; ni < 4; ni++) {
                const int d = wn + ni * 8 + tig * 2;
                float as0 = asrc[d], as1 = asrc[d + 1];
                float ad0 = adst[d], ad1 = adst[d + 1];
                sp0 += acc[mi][ni][0] * as0 + acc[mi][ni][1] * as1;
                sp1 += acc[mi][ni][2] * as0 + acc[mi][ni][3] * as1;
                tp0 += acc[mi][ni][0] * ad0 + acc[mi][ni][1] * ad1;
                tp1 += acc[mi][ni][2] * ad0 + acc[mi][ni][3] * ad1;
            }
            // reduce across the 4-lane tig group (lanes 4g..4g+3)
#pragma unroll
            for (int o = 1; o < 4; o <<= 1) {
                sp0 += __shfl_xor_sync(0xffffffffu, sp0, o);
                sp1 += __shfl_xor_sync(0xffffffffu, sp1, o);
                tp0 += __shfl_xor_sync(0xffffffffu, tp0, o);
                tp1 += __shfl_xor_sync(0xffffffffu, tp1, o);
            }
            if (tig == 0) {
                const int r0 = m0 + wm + mi * 16 + g;
                atomicAdd(&s[h * N_NODES + r0],     sp0);
                atomicAdd(&s[h * N_NODES + r0 + 8], sp1);
                atomicAdd(&t[h * N_NODES + r0],     tp0);
                atomicAdd(&t[h * N_NODES + r0 + 8], tp1);
            }
        }
    }
#undef K1_LOAD
}

// ---------------------------------------------------------------------------
// K3: attention from precompacted lists (R13-exact, frozen).
// ---------------------------------------------------------------------------
__global__ __launch_bounds__(256) void k3_attn(
    const int* __restrict__ nbr, const int* __restrict__ degv,
    const float* __restrict__ wh,
    const float* __restrict__ s, const float* __restrict__ t,
    __nv_bfloat16* __restrict__ h4a)
{
    __shared__ int   sidx[MAXDEG];
    __shared__ float sw[NHEADS * MAXDEG];
    __shared__ float srs[NHEADS];

    const int i   = blockIdx.x;
    const int tid = threadIdx.x;
    const int deg = degv[i];

    for (int j = tid; j < deg; j += 256) sidx[j] = nbr[(size_t)i * MAXDEG + j];
    __syncthreads();

    for (int m = tid; m < deg * NHEADS; m += 256) {
        int j = m >> 2;
        int h = m & 3;
        int jj = sidx[j];
        float e = s[h * N_NODES + i] + t[h * N_NODES + jj];
        e = e > 0.f ? e : LRELU_ALPHA * e;
        sw[h * MAXDEG + j] = e;
    }
    __syncthreads();

    const int warp = tid >> 5;
    const int lane = tid & 31;
    if (warp < NHEADS) {
        const int h = warp;
        float mx = -3.4e38f;
        for (int j = lane; j < deg; j += 32) mx = fmaxf(mx, sw[h * MAXDEG + j]);
#pragma unroll
        for (int o = 16; o; o >>= 1) mx = fmaxf(mx, __shfl_xor_sync(0xffffffffu, mx, o));
        float sum = 0.f;
        for (int j = lane; j < deg; j += 32) {
            float w = __expf(sw[h * MAXDEG + j] - mx);
            sw[h * MAXDEG + j] = w;
            sum += w;
        }
#pragma unroll
        for (int o = 16; o; o >>= 1) sum += __shfl_xor_sync(0xffffffffu, sum, o);
        if (lane == 0) srs[h] = (sum > 0.f) ? 1.f / sum : 0.f;
    }
    __syncthreads();

    const int h = tid >> 6;
    float acc = 0.f;
    const float* whb = wh + tid;
#pragma unroll 4
    for (int j = 0; j < deg; j++) {
        int jj = sidx[j];
        acc += sw[h * MAXDEG + j] * whb[(size_t)jj * NHID];
    }
    acc *= srs[h];
    acc = acc > 0.f ? acc : (__expf(acc) - 1.f);

    __nv_bfloat16 hi = __float2bfloat16(acc);
    __nv_bfloat16 lo = __float2bfloat16(acc - __bfloat162float(hi));
    __nv_bfloat16* base = h4a + (size_t)i * KCAT4 + tid;
    base[0]   = hi;
    base[256] = hi;
    base[512] = lo;
}

// ---------------------------------------------------------------------------
// K4: HMMA GEMM  out = elu(h' @ lin_w'^T + b)   (R13-exact)
// ---------------------------------------------------------------------------
#define BK4   32
#define SSTR4 20

__global__ __launch_bounds__(256) void k4_mma(
    const __nv_bfloat16* __restrict__ h4a, const __nv_bfloat16* __restrict__ b4,
    const float* __restrict__ lin_b, float* __restrict__ out)
{
    __shared__ u32 As[32][SSTR4];
    __shared__ u32 Bs[128][SSTR4];

    const int tid  = threadIdx.x;
    const int wid  = tid >> 5;
    const int lane = tid & 31;
    const int g    = lane >> 2;
    const int tig  = lane & 3;
    const int m0   = blockIdx.x * 32;
    const int wn   = wid * 16;

    float acc[2][2][4];
#pragma unroll
    for (int mi = 0; mi < 2; mi++)
#pragma unroll
        for (int ni = 0; ni < 2; ni++)
#pragma unroll
            for (int q = 0; q < 4; q++) acc[mi][ni][q] = 0.f;

    const int l_row = tid >> 2;
    const int l_wq  = (tid & 3) << 2;

    for (int kk = 0; kk < KCAT4; kk += BK4) {
        if (tid < 128) {
            uint4 va = *(const uint4*)(h4a + (size_t)(m0 + l_row) * KCAT4 + kk + l_wq * 2);
            *(uint4*)&As[l_row][l_wq] = va;
        }
#pragma unroll
        for (int it = 0; it < 2; it++) {
            int row = l_row + it * 64;
            uint4 vb = *(const uint4*)(b4 + (size_t)row * KCAT4 + kk + l_wq * 2);
            *(uint4*)&Bs[row][l_wq] = vb;
        }
        __syncthreads();

#pragma unroll
        for (int ks = 0; ks < 2; ks++) {
            const int kw = ks * 8;
            u32 a[2][4];
#pragma unroll
            for (int mi = 0; mi < 2; mi++) {
                const int r = mi * 16;
                a[mi][0] = As[r + g    ][kw + tig];
                a[mi][1] = As[r + g + 8][kw + tig];
                a[mi][2] = As[r + g    ][kw + tig + 4];
                a[mi][3] = As[r + g + 8][kw + tig + 4];
            }
            u32 b[2][2];
#pragma unroll
            for (int ni = 0; ni < 2; ni++) {
                const int n = wn + ni * 8 + g;
                b[ni][0] = Bs[n][kw + tig];
                b[ni][1] = Bs[n][kw + tig + 4];
            }
#pragma unroll
            for (int mi = 0; mi < 2; mi++)
#pragma unroll
                for (int ni = 0; ni < 2; ni++)
                    hmma16816(acc[mi][ni][0], acc[mi][ni][1],
                              acc[mi][ni][2], acc[mi][ni][3],
                              a[mi][0], a[mi][1], a[mi][2], a[mi][3],
                              b[ni][0], b[ni][1]);
        }
        __syncthreads();
    }

#pragma unroll
    for (int mi = 0; mi < 2; mi++) {
        const int r0 = m0 + mi * 16 + g;
#pragma unroll
        for (int ni = 0; ni < 2; ni++) {
            const int c0 = wn + ni * 8 + tig * 2;
            float b0 = lin_b[c0], b1 = lin_b[c0 + 1];
            float v0 = acc[mi][ni][0] + b0;
            float v1 = acc[mi][ni][1] + b1;
            float v2 = acc[mi][ni][2] + b0;
            float v3 = acc[mi][ni][3] + b1;
            v0 = v0 > 0.f ? v0 : (__expf(v0) - 1.f);
            v1 = v1 > 0.f ? v1 : (__expf(v1) - 1.f);
            v2 = v2 > 0.f ? v2 : (__expf(v2) - 1.f);
            v3 = v3 > 0.f ? v3 : (__expf(v3) - 1.f);
            *(float2*)(out + (size_t)r0 * NEMBED + c0) = make_float2(v0, v1);
            *(float2*)(out + (size_t)(r0 + 8) * NEMBED + c0) = make_float2(v2, v3);
        }
    }
}

// ---------------------------------------------------------------------------
extern "C" void kernel_launch(void* const* d_in, const int* in_sizes, int n_in,
                              void* d_out, int out_size)
{
    const float* x     = (const float*)d_in[0];
    const int*   adj   = (const int*)  d_in[1];
    const float* W     = (const float*)d_in[2];
    const float* a_src = (const float*)d_in[3];
    const float* a_dst = (const float*)d_in[4];
    const float* lin_w = (const float*)d_in[5];
    const float* lin_b = (const float*)d_in[6];
    float* out = (float*)d_out;

    float* whcat; cudaGetSymbolAddress((void**)&whcat, g_whcat);
    float* s;     cudaGetSymbolAddress((void**)&s, g_s);
    float* t;     cudaGetSymbolAddress((void**)&t, g_t);
    __nv_bfloat16* abf; cudaGetSymbolAddress((void**)&abf, g_abf);
    __nv_bfloat16* bbf; cudaGetSymbolAddress((void**)&bbf, g_bbf);
    __nv_bfloat16* h4a; cudaGetSymbolAddress((void**)&h4a, g_h4a);
    __nv_bfloat16* b4;  cudaGetSymbolAddress((void**)&b4, g_b4);
    int* nbr; cudaGetSymbolAddress((void**)&nbr, g_nbr);
    int* deg; cudaGetSymbolAddress((void**)&deg, g_deg);

    p_prep<<<PB_A + PB_B + PB_L + PB_Z, 256>>>(x, W, lin_w, abf, bbf, b4, s, t);

    k1_fused<<<NB_GEMM + N_NODES, 128>>>(abf, bbf, whcat, adj, nbr, deg,
                                         a_src, a_dst, s, t);

    k3_attn<<<N_NODES, 256>>>(nbr, deg, whcat, s, t, h4a);

    k4_mma<<<N_NODES / 32, 256>>>(h4a, b4, lin_b, out);
}

// round 16
// speedup vs baseline: 1.1943x; 1.0547x over previous
#include <cuda_runtime.h>
#include <cuda_bf16.h>

#define N_NODES 6144
#define NFEAT   512
#define NHID    256
#define NHEADS  4
#define DHEAD   64
#define NEMBED  128
#define LRELU_ALPHA 0.2f
#define MAXDEG  256
#define KCAT    1536           // logical K (3 * NFEAT) for the split-bf16 GEMM
#define KCATA   1024           // A' physical row: [x_hi | x_lo]
#define KCAT4   768            // logical K for k4 (3 * NHID)
#define KCAT4A  512            // h' physical row: [h_hi | h_lo]

typedef unsigned int u32;

// Scratch (device globals; no runtime allocation allowed)
__device__ float g_whcat[N_NODES * NHID];
__device__ float g_s[NHEADS * N_NODES];
__device__ float g_t[NHEADS * N_NODES];
__device__ __nv_bfloat16 g_abf[N_NODES * KCATA];  // [x_hi | x_lo]
__device__ __nv_bfloat16 g_bbf[NHID * KCAT];      // [w_hi | w_lo | w_hi]
__device__ __nv_bfloat16 g_h4a[N_NODES * KCAT4A]; // [h_hi | h_lo]
__device__ __nv_bfloat16 g_b4[NEMBED * KCAT4];    // [w_hi | w_lo | w_hi]
__device__ int g_nbr[N_NODES * MAXDEG];           // compacted neighbor lists
__device__ int g_deg[N_NODES];

// ---------------------------------------------------------------------------
__device__ __forceinline__ void hmma16816(
    float& c0, float& c1, float& c2, float& c3,
    u32 a0, u32 a1, u32 a2, u32 a3, u32 b0, u32 b1)
{
    asm volatile(
        "mma.sync.aligned.m16n8k16.row.col.f32.bf16.bf16.f32 "
        "{%0,%1,%2,%3}, {%4,%5,%6,%7}, {%8,%9}, {%0,%1,%2,%3};\n"
        : "+f"(c0), "+f"(c1), "+f"(c2), "+f"(c3)
        : "r"(a0), "r"(a1), "r"(a2), "r"(a3), "r"(b0), "r"(b1));
}
__device__ __forceinline__ void ldsm4(u32& r0, u32& r1, u32& r2, u32& r3, u32 addr)
{
    asm volatile("ldmatrix.sync.aligned.m8n8.x4.shared.b16 {%0,%1,%2,%3}, [%4];"
                 : "=r"(r0), "=r"(r1), "=r"(r2), "=r"(r3) : "r"(addr));
}
__device__ __forceinline__ void cp16(u32 saddr, const void* gptr)
{
    asm volatile("cp.async.cg.shared.global [%0], [%1], 16;" :: "r"(saddr), "l"(gptr));
}
#define CP_COMMIT() asm volatile("cp.async.commit_group;" ::: "memory")
#define CP_WAIT0()  asm volatile("cp.async.wait_group 0;" ::: "memory")
#define CP_WAIT1()  asm volatile("cp.async.wait_group 1;" ::: "memory")

__device__ __forceinline__ u32 smem_u32(const void* p)
{
    u32 a;
    asm("{ .reg .u64 t; cvta.to.shared.u64 t, %1; cvt.u32.u64 %0, t; }"
        : "=r"(a) : "l"(p));
    return a;
}

// ---------------------------------------------------------------------------
// P: split-bf16 preps + s/t zeroing fused in one launch, sectioned by blockIdx.
// ---------------------------------------------------------------------------
#define PB_A 3072
#define PB_B 512
#define PB_L 128
#define PB_Z 48

__global__ __launch_bounds__(256) void p_prep(
    const float* __restrict__ x, const float* __restrict__ W,
    const float* __restrict__ lin_w,
    __nv_bfloat16* __restrict__ abf, __nv_bfloat16* __restrict__ bbf,
    __nv_bfloat16* __restrict__ b4,
    float* __restrict__ s, float* __restrict__ t)
{
    const int b   = blockIdx.x;
    const int tid = threadIdx.x;

    if (b < PB_A) {
        int idx = b * 256 + tid;
        int m = idx >> 7;
        int kq = (idx & 127) << 2;
        float4 v = *(const float4*)(x + (size_t)m * NFEAT + kq);
        float vv[4] = {v.x, v.y, v.z, v.w};
        __nv_bfloat16 hi[4], lo[4];
#pragma unroll
        for (int i = 0; i < 4; i++) {
            hi[i] = __float2bfloat16(vv[i]);
            lo[i] = __float2bfloat16(vv[i] - __bfloat162float(hi[i]));
        }
        __nv_bfloat16* base = abf + (size_t)m * KCATA + kq;
        *(uint2*)(base)       = *(uint2*)hi;
        *(uint2*)(base + 512) = *(uint2*)lo;
    } else if (b < PB_A + PB_B) {
        int idx = (b - PB_A) * 256 + tid;
        int n = idx >> 9;
        int k = idx & 511;
        int h = n >> 6, d = n & 63;
        float v = W[((size_t)h * NFEAT + k) * DHEAD + d];
        __nv_bfloat16 hi = __float2bfloat16(v);
        __nv_bfloat16 lo = __float2bfloat16(v - __bfloat162float(hi));
        __nv_bfloat16* base = bbf + (size_t)n * KCAT + k;
        base[0]    = hi;
        base[512]  = lo;
        base[1024] = hi;
    } else if (b < PB_A + PB_B + PB_L) {
        int idx = (b - PB_A - PB_B) * 256 + tid;
        int n = idx >> 8;
        int k = idx & 255;
        float v = lin_w[(size_t)n * NHID + k];
        __nv_bfloat16 hi = __float2bfloat16(v);
        __nv_bfloat16 lo = __float2bfloat16(v - __bfloat162float(hi));
        __nv_bfloat16* base = b4 + (size_t)n * KCAT4 + k;
        base[0]   = hi;
        base[256] = lo;
        base[512] = hi;
    } else {
        int idx = (b - PB_A - PB_B - PB_L) * 256 + tid;
        float4 z = make_float4(0.f, 0.f, 0.f, 0.f);
        if (idx < 6144) ((float4*)s)[idx] = z;
        else            ((float4*)t)[idx - 6144] = z;
    }
}

// ---------------------------------------------------------------------------
// K1F: FUSED kernel (R13 schedule) + s/t epilogue (k2 folded).
// ---------------------------------------------------------------------------
#define BK      32
#define SSTR    20
#define K1_NIT  (KCAT / BK)
#define NB_GEMM 384

__global__ __launch_bounds__(128) void k1_fused(
    const __nv_bfloat16* __restrict__ abf, const __nv_bfloat16* __restrict__ bbf,
    float* __restrict__ C,
    const int* __restrict__ adj, int* __restrict__ nbr, int* __restrict__ deg,
    const float* __restrict__ a_src, const float* __restrict__ a_dst,
    float* __restrict__ s, float* __restrict__ t)
{
    __shared__ u32 As[2][64][SSTR];
    __shared__ u32 Bs[2][64][SSTR];

    const int bid = blockIdx.x;
    const int tid = threadIdx.x;

    if (bid >= NB_GEMM) {
        // ---------------- scan branch ----------------
        __shared__ int scount;
        const int i    = bid - NB_GEMM;
        const int lane = tid & 31;
        if (tid == 0) scount = 0;
        __syncthreads();

        const int4* arow = (const int4*)(adj + (size_t)i * N_NODES);
        int4 v[12];
#pragma unroll
        for (int q = 0; q < 12; q++) v[q] = arow[tid + q * 128];

        int cnt = 0;
#pragma unroll
        for (int q = 0; q < 12; q++)
            cnt += (v[q].x != 0) + (v[q].y != 0) + (v[q].z != 0) + (v[q].w != 0);

        int inc = cnt;
#pragma unroll
        for (int o = 1; o < 32; o <<= 1) {
            int nb = __shfl_up_sync(0xffffffffu, inc, o);
            if (lane >= o) inc += nb;
        }
        int excl = inc - cnt;
        int wtot = __shfl_sync(0xffffffffu, inc, 31);

        int wbase = 0;
        if (lane == 31 && wtot > 0) wbase = atomicAdd(&scount, wtot);
        wbase = __shfl_sync(0xffffffffu, wbase, 31);

        int* row = nbr + (size_t)i * MAXDEG;
        int p = wbase + excl;
#pragma unroll
        for (int q = 0; q < 12; q++) {
            int c = (tid + q * 128) * 4;
            if (v[q].x) { if (p < MAXDEG) row[p] = c + 0; p++; }
            if (v[q].y) { if (p < MAXDEG) row[p] = c + 1; p++; }
            if (v[q].z) { if (p < MAXDEG) row[p] = c + 2; p++; }
            if (v[q].w) { if (p < MAXDEG) row[p] = c + 3; p++; }
        }
        __syncthreads();
        if (tid == 0) deg[i] = min(scount, MAXDEG);
        return;
    }

    // ---------------- GEMM branch ----------------
    const int wid  = tid >> 5;
    const int lane = tid & 31;
    const int g    = lane >> 2;
    const int tig  = lane & 3;
    const int m0   = (bid >> 2) * 64;
    const int n0   = (bid & 3) * 64;       // == head * 64
    const int wm   = (wid & 1) * 32;
    const int wn   = (wid >> 1) * 32;

    const u32 sA = smem_u32(As);
    const u32 sB = smem_u32(Bs);

    float acc[2][4][4];
#pragma unroll
    for (int mi = 0; mi < 2; mi++)
#pragma unroll
        for (int ni = 0; ni < 4; ni++)
#pragma unroll
            for (int q = 0; q < 4; q++) acc[mi][ni][q] = 0.f;

    const int l_row = tid >> 2;
    const int l_wq  = (tid & 3) << 2;
    const int l_col = l_wq << 1;

    const u32 a_frag_off = ((u32)(wm + (lane & 15)) * SSTR + ((lane >> 4) << 2)) << 2;
    const u32 b_frag_off = ((u32)(wn + (lane & 7) + ((lane >> 4) << 3)) * SSTR
                            + (((lane >> 3) & 1) << 2)) << 2;

#define K1_LOAD(stg, kk)                                                        \
    do {                                                                        \
        const int akk = (kk) < 512 ? (kk) : (kk) - 512;                         \
        _Pragma("unroll")                                                       \
        for (int ps = 0; ps < 2; ps++) {                                        \
            int row = l_row + ps * 32;                                          \
            cp16(sA + (((stg) * 64 + row) * SSTR + l_wq) * 4,                   \
                 abf + (size_t)(m0 + row) * KCATA + akk + l_col);               \
            cp16(sB + (((stg) * 64 + row) * SSTR + l_wq) * 4,                   \
                 bbf + (size_t)(n0 + row) * KCAT + (kk) + l_col);               \
        }                                                                       \
        CP_COMMIT();                                                            \
    } while (0)

    K1_LOAD(0, 0);

    for (int it = 0; it < K1_NIT; it++) {
        const int buf = it & 1;
        if (it + 1 < K1_NIT) {
            K1_LOAD(buf ^ 1, (it + 1) * BK);
            CP_WAIT1();
        } else {
            CP_WAIT0();
        }
        __syncthreads();

        const u32 aB = sA + (u32)(buf * 64 * SSTR * 4) + a_frag_off;
        const u32 bB = sB + (u32)(buf * 64 * SSTR * 4) + b_frag_off;
#pragma unroll
        for (int ks = 0; ks < 2; ks++) {
            const u32 kOff = (u32)(ks * 8 * 4);
            u32 a[2][4];
#pragma unroll
            for (int mi = 0; mi < 2; mi++)
                ldsm4(a[mi][0], a[mi][1], a[mi][2], a[mi][3],
                      aB + (u32)(mi * 16 * SSTR * 4) + kOff);
            u32 b[2][4];
#pragma unroll
            for (int nj = 0; nj < 2; nj++)
                ldsm4(b[nj][0], b[nj][1], b[nj][2], b[nj][3],
                      bB + (u32)(nj * 16 * SSTR * 4) + kOff);
#pragma unroll
            for (int mi = 0; mi < 2; mi++)
#pragma unroll
                for (int nj = 0; nj < 2; nj++) {
                    hmma16816(acc[mi][nj*2+0][0], acc[mi][nj*2+0][1],
                              acc[mi][nj*2+0][2], acc[mi][nj*2+0][3],
                              a[mi][0], a[mi][1], a[mi][2], a[mi][3],
                              b[nj][0], b[nj][1]);
                    hmma16816(acc[mi][nj*2+1][0], acc[mi][nj*2+1][1],
                              acc[mi][nj*2+1][2], acc[mi][nj*2+1][3],
                              a[mi][0], a[mi][1], a[mi][2], a[mi][3],
                              b[nj][2], b[nj][3]);
                }
        }
        __syncthreads();
    }

    // ---- epilogue 1: store whcat tile ----
#pragma unroll
    for (int mi = 0; mi < 2; mi++) {
        const int r0 = m0 + wm + mi * 16 + g;
#pragma unroll
        for (int ni = 0; ni < 4; ni++) {
            const int c0 = n0 + wn + ni * 8 + tig * 2;
            *(float2*)(C + (size_t)r0 * NHID + c0) =
                make_float2(acc[mi][ni][0], acc[mi][ni][1]);
            *(float2*)(C + (size_t)(r0 + 8) * NHID + c0) =
                make_float2(acc[mi][ni][2], acc[mi][ni][3]);
        }
    }

    // ---- epilogue 2 (k2 folded): partial s/t for this block's head ----
    {
        const int h = bid & 3;
        const float* asrc = a_src + h * DHEAD;
        const float* adst = a_dst + h * DHEAD;
#pragma unroll
        for (int mi = 0; mi < 2; mi++) {
            float sp0 = 0.f, sp1 = 0.f, tp0 = 0.f, tp1 = 0.f;
#pragma unroll
            for (int ni = 0; ni < 4; ni++) {
                const int d = wn + ni * 8 + tig * 2;
                float as0 = asrc[d], as1 = asrc[d + 1];
                float ad0 = adst[d], ad1 = adst[d + 1];
                sp0 += acc[mi][ni][0] * as0 + acc[mi][ni][1] * as1;
                sp1 += acc[mi][ni][2] * as0 + acc[mi][ni][3] * as1;
                tp0 += acc[mi][ni][0] * ad0 + acc[mi][ni][1] * ad1;
                tp1 += acc[mi][ni][2] * ad0 + acc[mi][ni][3] * ad1;
            }
#pragma unroll
            for (int o = 1; o < 4; o <<= 1) {
                sp0 += __shfl_xor_sync(0xffffffffu, sp0, o);
                sp1 += __shfl_xor_sync(0xffffffffu, sp1, o);
                tp0 += __shfl_xor_sync(0xffffffffu, tp0, o);
                tp1 += __shfl_xor_sync(0xffffffffu, tp1, o);
            }
            if (tig == 0) {
                const int r0 = m0 + wm + mi * 16 + g;
                atomicAdd(&s[h * N_NODES + r0],     sp0);
                atomicAdd(&s[h * N_NODES + r0 + 8], sp1);
                atomicAdd(&t[h * N_NODES + r0],     tp0);
                atomicAdd(&t[h * N_NODES + r0 + 8], tp1);
            }
        }
    }
#undef K1_LOAD
}

// ---------------------------------------------------------------------------
// K3: attention from precompacted lists (R13 core, frozen).
//     Epilogue writes dedup'd h' layout [h_hi | h_lo] (512/row).
// ---------------------------------------------------------------------------
__global__ __launch_bounds__(256) void k3_attn(
    const int* __restrict__ nbr, const int* __restrict__ degv,
    const float* __restrict__ wh,
    const float* __restrict__ s, const float* __restrict__ t,
    __nv_bfloat16* __restrict__ h4a)
{
    __shared__ int   sidx[MAXDEG];
    __shared__ float sw[NHEADS * MAXDEG];
    __shared__ float srs[NHEADS];

    const int i   = blockIdx.x;
    const int tid = threadIdx.x;
    const int deg = degv[i];

    for (int j = tid; j < deg; j += 256) sidx[j] = nbr[(size_t)i * MAXDEG + j];
    __syncthreads();

    for (int m = tid; m < deg * NHEADS; m += 256) {
        int j = m >> 2;
        int h = m & 3;
        int jj = sidx[j];
        float e = s[h * N_NODES + i] + t[h * N_NODES + jj];
        e = e > 0.f ? e : LRELU_ALPHA * e;
        sw[h * MAXDEG + j] = e;
    }
    __syncthreads();

    const int warp = tid >> 5;
    const int lane = tid & 31;
    if (warp < NHEADS) {
        const int h = warp;
        float mx = -3.4e38f;
        for (int j = lane; j < deg; j += 32) mx = fmaxf(mx, sw[h * MAXDEG + j]);
#pragma unroll
        for (int o = 16; o; o >>= 1) mx = fmaxf(mx, __shfl_xor_sync(0xffffffffu, mx, o));
        float sum = 0.f;
        for (int j = lane; j < deg; j += 32) {
            float w = __expf(sw[h * MAXDEG + j] - mx);
            sw[h * MAXDEG + j] = w;
            sum += w;
        }
#pragma unroll
        for (int o = 16; o; o >>= 1) sum += __shfl_xor_sync(0xffffffffu, sum, o);
        if (lane == 0) srs[h] = (sum > 0.f) ? 1.f / sum : 0.f;
    }
    __syncthreads();

    const int h = tid >> 6;
    float acc = 0.f;
    const float* whb = wh + tid;
#pragma unroll 4
    for (int j = 0; j < deg; j++) {
        int jj = sidx[j];
        acc += sw[h * MAXDEG + j] * whb[(size_t)jj * NHID];
    }
    acc *= srs[h];
    acc = acc > 0.f ? acc : (__expf(acc) - 1.f);

    __nv_bfloat16 hi = __float2bfloat16(acc);
    __nv_bfloat16 lo = __float2bfloat16(acc - __bfloat162float(hi));
    __nv_bfloat16* base = h4a + (size_t)i * KCAT4A + tid;
    base[0]   = hi;
    base[256] = lo;
}

// ---------------------------------------------------------------------------
// K4: HMMA GEMM  out = elu(h' @ lin_w'^T + b)
//     Clone of the proven k1 GEMM: BM=64, BN=64, BK=32, 128 threads,
//     2-stage cp.async + ldmatrix. Grid (96, 2) = 192 blocks. K=768 logical.
// ---------------------------------------------------------------------------
__global__ __launch_bounds__(128) void k4_mma(
    const __nv_bfloat16* __restrict__ h4a, const __nv_bfloat16* __restrict__ b4,
    const float* __restrict__ lin_b, float* __restrict__ out)
{
    __shared__ u32 As[2][64][SSTR];
    __shared__ u32 Bs[2][64][SSTR];

    const int tid  = threadIdx.x;
    const int wid  = tid >> 5;
    const int lane = tid & 31;
    const int g    = lane >> 2;
    const int tig  = lane & 3;
    const int m0   = blockIdx.x * 64;
    const int n0   = blockIdx.y * 64;
    const int wm   = (wid & 1) * 32;
    const int wn   = (wid >> 1) * 32;

    const u32 sA = smem_u32(As);
    const u32 sB = smem_u32(Bs);

    float acc[2][4][4];
#pragma unroll
    for (int mi = 0; mi < 2; mi++)
#pragma unroll
        for (int ni = 0; ni < 4; ni++)
#pragma unroll
            for (int q = 0; q < 4; q++) acc[mi][ni][q] = 0.f;

    const int l_row = tid >> 2;
    const int l_wq  = (tid & 3) << 2;
    const int l_col = l_wq << 1;

    const u32 a_frag_off = ((u32)(wm + (lane & 15)) * SSTR + ((lane >> 4) << 2)) << 2;
    const u32 b_frag_off = ((u32)(wn + (lane & 7) + ((lane >> 4) << 3)) * SSTR
                            + (((lane >> 3) & 1) << 2)) << 2;

    // h' dedup remap: kk<256 -> kk (h_hi|w_hi); [256,512) -> kk-256 (h_hi|w_lo);
    //                 [512,768) -> kk-256 (h_lo|w_hi)
#define K4_LOAD(stg, kk)                                                        \
    do {                                                                        \
        const int akk = (kk) < 256 ? (kk) : (kk) - 256;                         \
        _Pragma("unroll")                                                       \
        for (int ps = 0; ps < 2; ps++) {                                        \
            int row = l_row + ps * 32;                                          \
            cp16(sA + (((stg) * 64 + row) * SSTR + l_wq) * 4,                   \
                 h4a + (size_t)(m0 + row) * KCAT4A + akk + l_col);              \
            cp16(sB + (((stg) * 64 + row) * SSTR + l_wq) * 4,                   \
                 b4 + (size_t)(n0 + row) * KCAT4 + (kk) + l_col);               \
        }                                                                       \
        CP_COMMIT();                                                            \
    } while (0)

    const int NIT = KCAT4 / BK;   // 24
    K4_LOAD(0, 0);

    for (int it = 0; it < NIT; it++) {
        const int buf = it & 1;
        if (it + 1 < NIT) {
            K4_LOAD(buf ^ 1, (it + 1) * BK);
            CP_WAIT1();
        } else {
            CP_WAIT0();
        }
        __syncthreads();

        const u32 aB = sA + (u32)(buf * 64 * SSTR * 4) + a_frag_off;
        const u32 bB = sB + (u32)(buf * 64 * SSTR * 4) + b_frag_off;
#pragma unroll
        for (int ks = 0; ks < 2; ks++) {
            const u32 kOff = (u32)(ks * 8 * 4);
            u32 a[2][4];
#pragma unroll
            for (int mi = 0; mi < 2; mi++)
                ldsm4(a[mi][0], a[mi][1], a[mi][2], a[mi][3],
                      aB + (u32)(mi * 16 * SSTR * 4) + kOff);
            u32 b[2][4];
#pragma unroll
            for (int nj = 0; nj < 2; nj++)
                ldsm4(b[nj][0], b[nj][1], b[nj][2], b[nj][3],
                      bB + (u32)(nj * 16 * SSTR * 4) + kOff);
#pragma unroll
            for (int mi = 0; mi < 2; mi++)
#pragma unroll
                for (int nj = 0; nj < 2; nj++) {
                    hmma16816(acc[mi][nj*2+0][0], acc[mi][nj*2+0][1],
                              acc[mi][nj*2+0][2], acc[mi][nj*2+0][3],
                              a[mi][0], a[mi][1], a[mi][2], a[mi][3],
                              b[nj][0], b[nj][1]);
                    hmma16816(acc[mi][nj*2+1][0], acc[mi][nj*2+1][1],
                              acc[mi][nj*2+1][2], acc[mi][nj*2+1][3],
                              a[mi][0], a[mi][1], a[mi][2], a[mi][3],
                              b[nj][2], b[nj][3]);
                }
        }
        __syncthreads();
    }

    // epilogue: bias + ELU
#pragma unroll
    for (int mi = 0; mi < 2; mi++) {
        const int r0 = m0 + wm + mi * 16 + g;
#pragma unroll
        for (int ni = 0; ni < 4; ni++) {
            const int c0 = n0 + wn + ni * 8 + tig * 2;
            float b0 = lin_b[c0], b1 = lin_b[c0 + 1];
            float v0 = acc[mi][ni][0] + b0;
            float v1 = acc[mi][ni][1] + b1;
            float v2 = acc[mi][ni][2] + b0;
            float v3 = acc[mi][ni][3] + b1;
            v0 = v0 > 0.f ? v0 : (__expf(v0) - 1.f);
            v1 = v1 > 0.f ? v1 : (__expf(v1) - 1.f);
            v2 = v2 > 0.f ? v2 : (__expf(v2) - 1.f);
            v3 = v3 > 0.f ? v3 : (__expf(v3) - 1.f);
            *(float2*)(out + (size_t)r0 * NEMBED + c0) = make_float2(v0, v1);
            *(float2*)(out + (size_t)(r0 + 8) * NEMBED + c0) = make_float2(v2, v3);
        }
    }
#undef K4_LOAD
}

// ---------------------------------------------------------------------------
extern "C" void kernel_launch(void* const* d_in, const int* in_sizes, int n_in,
                              void* d_out, int out_size)
{
    const float* x     = (const float*)d_in[0];
    const int*   adj   = (const int*)  d_in[1];
    const float* W     = (const float*)d_in[2];
    const float* a_src = (const float*)d_in[3];
    const float* a_dst = (const float*)d_in[4];
    const float* lin_w = (const float*)d_in[5];
    const float* lin_b = (const float*)d_in[6];
    float* out = (float*)d_out;

    float* whcat; cudaGetSymbolAddress((void**)&whcat, g_whcat);
    float* s;     cudaGetSymbolAddress((void**)&s, g_s);
    float* t;     cudaGetSymbolAddress((void**)&t, g_t);
    __nv_bfloat16* abf; cudaGetSymbolAddress((void**)&abf, g_abf);
    __nv_bfloat16* bbf; cudaGetSymbolAddress((void**)&bbf, g_bbf);
    __nv_bfloat16* h4a; cudaGetSymbolAddress((void**)&h4a, g_h4a);
    __nv_bfloat16* b4;  cudaGetSymbolAddress((void**)&b4, g_b4);
    int* nbr; cudaGetSymbolAddress((void**)&nbr, g_nbr);
    int* deg; cudaGetSymbolAddress((void**)&deg, g_deg);

    p_prep<<<PB_A + PB_B + PB_L + PB_Z, 256>>>(x, W, lin_w, abf, bbf, b4, s, t);

    k1_fused<<<NB_GEMM + N_NODES, 128>>>(abf, bbf, whcat, adj, nbr, deg,
                                         a_src, a_dst, s, t);

    k3_attn<<<N_NODES, 256>>>(nbr, deg, whcat, s, t, h4a);

    dim3 g4(N_NODES / 64, NEMBED / 64);
    k4_mma<<<g4, 128>>>(h4a, b4, lin_b, out);
}